// round 2
// baseline (speedup 1.0000x reference)
#include <cuda_runtime.h>

// Degree-3 SH constants (match reference)
#define SH_C0 0.28209479177387814f
#define SH_C1 0.4886025119029199f
#define SH_C2_0 1.0925484305920792f
#define SH_C2_1 (-1.0925484305920792f)
#define SH_C2_2 0.31539156525252005f
#define SH_C2_3 (-1.0925484305920792f)
#define SH_C2_4 0.5462742152960396f
#define SH_C3_0 (-0.5900435899266435f)
#define SH_C3_1 2.890611442640554f
#define SH_C3_2 (-0.4570457994644658f)
#define SH_C3_3 0.3731763325901154f
#define SH_C3_4 (-0.4570457994644658f)
#define SH_C3_5 1.445305721320277f
#define SH_C3_6 (-0.5900435899266435f)

// SMEM row layout (stride 53, conflict-free: 53 mod 32 = 21, odd):
//   [0:3)  mean xyz
//   [3:6)  fdc
//   [6:51) frest (45 floats)
//   [51]   opacity
#define ROW_STRIDE 53
#define BLOCK_THREADS 128

__global__ void __launch_bounds__(BLOCK_THREADS)
sh_gather_staged_kernel(const float* __restrict__ means,
                        const float* __restrict__ fdc,
                        const float* __restrict__ frest,
                        const float* __restrict__ opac,
                        const float* __restrict__ c2w,
                        const int*   __restrict__ mask_idx,
                        const int*   __restrict__ step_p,
                        float* __restrict__ out,
                        int M)
{
    __shared__ float s[BLOCK_THREADS * ROW_STRIDE];

    const int warp = threadIdx.x >> 5;
    const int lane = threadIdx.x & 31;
    const int rowbase = blockIdx.x * BLOCK_THREADS + warp * 32;  // first row of this warp
    const int myrow = rowbase + lane;

    // each lane reads its own index (coalesced), broadcast later via shfl
    const int j_lane = (myrow < M) ? mask_idx[myrow] : 0;

    float* swarp = &s[(warp * 32) * ROW_STRIDE];

    // ---- Stage 32 rows cooperatively: all lanes read CONSECUTIVE floats of one row ----
    #pragma unroll 4
    for (int r = 0; r < 32; r++) {
        if (rowbase + r >= M) break;  // uniform across warp
        const int j = __shfl_sync(0xffffffffu, j_lane, r);
        const float* __restrict__ fr = frest + (long long)j * 45;
        float* srow = swarp + r * ROW_STRIDE;

        // round 1: frest[0..31] -> smem[6..37]  (128B contiguous, <=2 lines)
        srow[6 + lane] = __ldg(&fr[lane]);

        // round 2: frest[32..44], mean, fdc, opac  (each a small contiguous run)
        float v; int dst;
        if (lane < 13)       { v = __ldg(&fr[32 + lane]);                        dst = 38 + lane; }
        else if (lane < 16)  { v = __ldg(&means[(long long)j * 3 + (lane - 13)]); dst = lane - 13; }
        else if (lane < 19)  { v = __ldg(&fdc[(long long)j * 3 + (lane - 16)]);   dst = 3 + (lane - 16); }
        else if (lane == 19) { v = __ldg(&opac[j]);                               dst = 51; }
        else                 { v = 0.0f;                                          dst = 52; }  // scratch slot
        if (lane < 20) srow[dst] = v;
    }
    __syncwarp();

    if (myrow >= M) return;

    // ---- Compute phase: one thread per row, all data from SMEM (conflict-free LDS) ----
    const float* srow = swarp + lane * ROW_STRIDE;

    const float cx = __ldg(&c2w[3]);
    const float cy = __ldg(&c2w[7]);
    const float cz = __ldg(&c2w[11]);

    float x = srow[0] - cx;
    float y = srow[1] - cy;
    float z = srow[2] - cz;
    const float inv = rsqrtf(x * x + y * y + z * z);
    x *= inv; y *= inv; z *= inv;

    int n = __ldg(step_p) / 1000;
    if (n > 3) n = 3;

    float r = SH_C0 * srow[3];
    float g = SH_C0 * srow[4];
    float b = SH_C0 * srow[5];

    const float* fr = srow + 6;  // 45 frest floats

    if (n >= 1) {
        const float b1 = -SH_C1 * y;
        const float b2 =  SH_C1 * z;
        const float b3 = -SH_C1 * x;
        r = fmaf(b1, fr[0], r); g = fmaf(b1, fr[1], g); b = fmaf(b1, fr[2], b);
        r = fmaf(b2, fr[3], r); g = fmaf(b2, fr[4], g); b = fmaf(b2, fr[5], b);
        r = fmaf(b3, fr[6], r); g = fmaf(b3, fr[7], g); b = fmaf(b3, fr[8], b);
    }
    if (n >= 2) {
        const float xx = x * x, yy = y * y, zz = z * z;
        const float xy = x * y, yz = y * z, xz = x * z;
        const float b4 = SH_C2_0 * xy;
        const float b5 = SH_C2_1 * yz;
        const float b6 = SH_C2_2 * (2.0f * zz - xx - yy);
        const float b7 = SH_C2_3 * xz;
        const float b8 = SH_C2_4 * (xx - yy);
        r = fmaf(b4, fr[ 9], r); g = fmaf(b4, fr[10], g); b = fmaf(b4, fr[11], b);
        r = fmaf(b5, fr[12], r); g = fmaf(b5, fr[13], g); b = fmaf(b5, fr[14], b);
        r = fmaf(b6, fr[15], r); g = fmaf(b6, fr[16], g); b = fmaf(b6, fr[17], b);
        r = fmaf(b7, fr[18], r); g = fmaf(b7, fr[19], g); b = fmaf(b7, fr[20], b);
        r = fmaf(b8, fr[21], r); g = fmaf(b8, fr[22], g); b = fmaf(b8, fr[23], b);
        if (n >= 3) {
            const float b9  = SH_C3_0 * y * (3.0f * xx - yy);
            const float b10 = SH_C3_1 * xy * z;
            const float b11 = SH_C3_2 * y * (4.0f * zz - xx - yy);
            const float b12 = SH_C3_3 * z * (2.0f * zz - 3.0f * xx - 3.0f * yy);
            const float b13 = SH_C3_4 * x * (4.0f * zz - xx - yy);
            const float b14 = SH_C3_5 * z * (xx - yy);
            const float b15 = SH_C3_6 * x * (xx - 3.0f * yy);
            r = fmaf(b9,  fr[24], r); g = fmaf(b9,  fr[25], g); b = fmaf(b9,  fr[26], b);
            r = fmaf(b10, fr[27], r); g = fmaf(b10, fr[28], g); b = fmaf(b10, fr[29], b);
            r = fmaf(b11, fr[30], r); g = fmaf(b11, fr[31], g); b = fmaf(b11, fr[32], b);
            r = fmaf(b12, fr[33], r); g = fmaf(b12, fr[34], g); b = fmaf(b12, fr[35], b);
            r = fmaf(b13, fr[36], r); g = fmaf(b13, fr[37], g); b = fmaf(b13, fr[38], b);
            r = fmaf(b14, fr[39], r); g = fmaf(b14, fr[40], g); b = fmaf(b14, fr[41], b);
            r = fmaf(b15, fr[42], r); g = fmaf(b15, fr[43], g); b = fmaf(b15, fr[44], b);
        }
    }

    const int i = myrow;
    out[3 * i + 0] = fmaxf(r + 0.5f, 0.0f);
    out[3 * i + 1] = fmaxf(g + 0.5f, 0.0f);
    out[3 * i + 2] = fmaxf(b + 0.5f, 0.0f);
    out[(long long)3 * M + i] = srow[51];
}

extern "C" void kernel_launch(void* const* d_in, const int* in_sizes, int n_in,
                              void* d_out, int out_size)
{
    const float* means = (const float*)d_in[0];
    const float* fdc   = (const float*)d_in[1];
    const float* frest = (const float*)d_in[2];
    const float* opac  = (const float*)d_in[3];
    const float* c2w   = (const float*)d_in[4];
    const int*   midx  = (const int*)  d_in[5];
    const int*   step  = (const int*)  d_in[6];
    float*       out   = (float*)d_out;

    const int M = in_sizes[5];
    const int blocks = (M + BLOCK_THREADS - 1) / BLOCK_THREADS;
    sh_gather_staged_kernel<<<blocks, BLOCK_THREADS>>>(means, fdc, frest, opac, c2w, midx, step, out, M);
}